// round 3
// baseline (speedup 1.0000x reference)
#include <cuda_runtime.h>

// ---------------------------------------------------------------------------
// SSIM loss, single fused kernel:
//   32x64 output tiles, 74x42 halo in dynamic smem
//   horizontal 11-tap Gaussian (FFMA-imm) on 5 channels -> smem
//   vertical 11-tap Gaussian + SSIM + clip + block reduce
//   128-slot double atomics + last-block-done finalization (self-resetting)
// ---------------------------------------------------------------------------

#define IMGW 512
#define IMGH 512
#define TW   32
#define TH   64
#define HALO 5
#define HW   (TW + 2*HALO)   // 42
#define HR   (TH + 2*HALO)   // 74
#define NTHREADS 512
#define GX (IMGW / TW)       // 16
#define GY (IMGH / TH)       // 8
#define GZ 48                // 16*3
#define NBLOCKS (GX * GY * GZ)   // 6144
#define NSLOT 128

// smem layout (floats)
#define S1_OFF  0
#define S2_OFF  (HR * HW)                    // 3108
#define HB_OFF  (2 * HR * HW)                // 6216
#define HB_CH   (HR * TW)                    // 2368
#define WS_OFF  (HB_OFF + 5 * HB_CH)         // 18056
#define SMEM_FLOATS (WS_OFF + 16)
#define SMEM_BYTES  (SMEM_FLOATS * 4)        // 72288

// Normalized 11-tap Gaussian, sigma=1.5
#define W0 0.00102838f
#define W1 0.00759876f
#define W2 0.03600077f
#define W3 0.10936069f
#define W4 0.21300554f
#define W5 0.26601173f

__device__ double   g_slots[NSLOT];   // zero-init at load; self-reset per run
__device__ unsigned g_count;          // zero-init at load; self-reset per run

__device__ __forceinline__ int reflect_idx(int i, int n) {
    if (i < 0) i = -i;
    if (i >= n) i = 2 * n - 2 - i;
    return i;
}

__device__ __forceinline__ constexpr float WT(int k) {
    return (k == 0 || k == 10) ? W0
         : (k == 1 || k == 9)  ? W1
         : (k == 2 || k == 8)  ? W2
         : (k == 3 || k == 7)  ? W3
         : (k == 4 || k == 6)  ? W4
         : W5;
}

__global__ __launch_bounds__(NTHREADS)
void ssim_fused_kernel(const float* __restrict__ img1,
                       const float* __restrict__ img2,
                       float* __restrict__ out) {
    extern __shared__ float smem[];
    float* s1 = smem + S1_OFF;
    float* s2 = smem + S2_OFF;
    float* hb = smem + HB_OFF;         // 5 channels of HR x TW
    float* ws = smem + WS_OFF;

    const int tid = threadIdx.x;
    const int img = blockIdx.z;
    const int tx0 = blockIdx.x * TW;
    const int ty0 = blockIdx.y * TH;

    const float* a = img1 + (size_t)img * (IMGW * IMGH);
    const float* b = img2 + (size_t)img * (IMGW * IMGH);

    // ---- load halo tile (reflect padding) ----
    for (int idx = tid; idx < HR * HW; idx += NTHREADS) {
        int r = idx / HW;
        int c = idx - r * HW;
        int gy = reflect_idx(ty0 + r - HALO, IMGH);
        int gx = reflect_idx(tx0 + c - HALO, IMGW);
        s1[idx] = a[gy * IMGW + gx];
        s2[idx] = b[gy * IMGW + gx];
    }
    __syncthreads();

    // ---- horizontal pass: HR rows x 8 col-groups of 4 = 592 tasks ----
    for (int task = tid; task < HR * (TW / 4); task += NTHREADS) {
        int r  = task >> 3;
        int c0 = (task & 7) << 2;
        const float* p1 = s1 + r * HW + c0;
        const float* p2 = s2 + r * HW + c0;

        float va[14], vb[14], aa[14], bb[14], ab[14];
#pragma unroll
        for (int i = 0; i < 14; i++) {
            float av = p1[i];
            float bv = p2[i];
            va[i] = av; vb[i] = bv;
            aa[i] = av * av;
            bb[i] = bv * bv;
            ab[i] = av * bv;
        }

        float v1[4]  = {0.f, 0.f, 0.f, 0.f};
        float v2[4]  = {0.f, 0.f, 0.f, 0.f};
        float v11[4] = {0.f, 0.f, 0.f, 0.f};
        float v22[4] = {0.f, 0.f, 0.f, 0.f};
        float v12[4] = {0.f, 0.f, 0.f, 0.f};
#pragma unroll
        for (int k = 0; k < 11; k++) {
            const float wk = WT(k);   // literal -> FFMA-imm (rt 1)
#pragma unroll
            for (int j = 0; j < 4; j++) {
                v1[j]  = fmaf(wk, va[j + k], v1[j]);
                v2[j]  = fmaf(wk, vb[j + k], v2[j]);
                v11[j] = fmaf(wk, aa[j + k], v11[j]);
                v22[j] = fmaf(wk, bb[j + k], v22[j]);
                v12[j] = fmaf(wk, ab[j + k], v12[j]);
            }
        }
        int o = r * TW + c0;
        *(float4*)&hb[0 * HB_CH + o] = make_float4(v1[0],  v1[1],  v1[2],  v1[3]);
        *(float4*)&hb[1 * HB_CH + o] = make_float4(v2[0],  v2[1],  v2[2],  v2[3]);
        *(float4*)&hb[2 * HB_CH + o] = make_float4(v11[0], v11[1], v11[2], v11[3]);
        *(float4*)&hb[3 * HB_CH + o] = make_float4(v22[0], v22[1], v22[2], v22[3]);
        *(float4*)&hb[4 * HB_CH + o] = make_float4(v12[0], v12[1], v12[2], v12[3]);
    }
    __syncthreads();

    // ---- vertical pass + SSIM: 32 cols x 16 strips of 4 rows ----
    const int tx = tid & 31;
    const int r0 = (tid >> 5) << 2;   // 0,4,...,60

    float m[5][4];
#pragma unroll
    for (int c = 0; c < 5; c++) {
        const float* hc = hb + c * HB_CH;
        float acc0 = 0.f, acc1 = 0.f, acc2 = 0.f, acc3 = 0.f;
#pragma unroll
        for (int k = 0; k < 14; k++) {
            float hv = hc[(r0 + k) * TW + tx];
            if (k <= 10)           acc0 = fmaf(WT(k),     hv, acc0);
            if (k >= 1 && k <= 11) acc1 = fmaf(WT(k - 1), hv, acc1);
            if (k >= 2 && k <= 12) acc2 = fmaf(WT(k - 2), hv, acc2);
            if (k >= 3)            acc3 = fmaf(WT(k - 3), hv, acc3);
        }
        m[c][0] = acc0; m[c][1] = acc1; m[c][2] = acc2; m[c][3] = acc3;
    }

    const float C1 = 1e-4f;
    const float C2 = 9e-4f;
    float lsum = 0.f;
#pragma unroll
    for (int j = 0; j < 4; j++) {
        float mu1 = m[0][j], mu2 = m[1][j];
        float e11 = m[2][j], e22 = m[3][j], e12 = m[4][j];
        float mu1sq = mu1 * mu1;
        float mu2sq = mu2 * mu2;
        float mu12  = mu1 * mu2;
        float sg1  = e11 - mu1sq;
        float sg2  = e22 - mu2sq;
        float sg12 = e12 - mu12;
        float num = fmaf(2.f, mu12, C1) * fmaf(2.f, sg12, C2);
        float den = (mu1sq + mu2sq + C1) * (sg1 + sg2 + C2);
        float v = __fdividef(num, den);
        v = fminf(fmaxf(v, 0.f), 1.f);
        lsum += v;
    }

    // ---- block reduction ----
#pragma unroll
    for (int off = 16; off > 0; off >>= 1)
        lsum += __shfl_xor_sync(0xffffffff, lsum, off);
    if ((tid & 31) == 0) ws[tid >> 5] = lsum;
    __syncthreads();

    __shared__ int s_isLast;
    if (tid == 0) {
        float s = 0.f;
#pragma unroll
        for (int i = 0; i < NTHREADS / 32; i++) s += ws[i];
        const int bid = blockIdx.x + GX * (blockIdx.y + GY * blockIdx.z);
        atomicAdd(&g_slots[bid & (NSLOT - 1)], (double)s);
        __threadfence();
        unsigned old = atomicAdd(&g_count, 1u);
        s_isLast = (old == NBLOCKS - 1);
    }
    __syncthreads();

    // ---- last block: finalize + reset for next graph replay ----
    if (s_isLast) {
        double v = 0.0;
        if (tid < NSLOT) v = ((volatile double*)g_slots)[tid];
#pragma unroll
        for (int off = 16; off > 0; off >>= 1)
            v += __shfl_xor_sync(0xffffffff, v, off);
        __shared__ double dsum[4];
        if (tid < NSLOT && (tid & 31) == 0) dsum[tid >> 5] = v;
        __syncthreads();
        if (tid == 0) {
            double total = dsum[0] + dsum[1] + dsum[2] + dsum[3];
            const double npix = 16.0 * 3.0 * 512.0 * 512.0;
            out[0] = (float)(1.0 - total / npix);
            g_count = 0;
        }
        if (tid < NSLOT) g_slots[tid] = 0.0;
    }
}

extern "C" void kernel_launch(void* const* d_in, const int* in_sizes, int n_in,
                              void* d_out, int out_size) {
    const float* img1 = (const float*)d_in[0];
    const float* img2 = (const float*)d_in[1];
    float* out = (float*)d_out;

    cudaFuncSetAttribute(ssim_fused_kernel,
                         cudaFuncAttributeMaxDynamicSharedMemorySize,
                         SMEM_BYTES);
    dim3 grid(GX, GY, GZ);
    ssim_fused_kernel<<<grid, NTHREADS, SMEM_BYTES>>>(img1, img2, out);
}

// round 4
// speedup vs baseline: 1.2021x; 1.2021x over previous
#include <cuda_runtime.h>

// ---------------------------------------------------------------------------
// SSIM loss, single fused kernel, occupancy+vector-load tuned:
//   32x32 output tiles, 42x44(padded) halo in static smem
//   horizontal 11-tap Gaussian (FFMA-imm) on 5 channels -> smem (SoA, STS.128)
//   vertical 11-tap Gaussian + SSIM + clip + block reduce
//   128-slot double atomics + last-block-done finalization (self-resetting)
//   __launch_bounds__(256,5): 5 CTA/SM (40 warps) instead of reg-limited 4
// ---------------------------------------------------------------------------

#define IMGW 512
#define IMGH 512
#define TW   32
#define TH   32
#define HALO 5
#define HW   42              // logical halo width
#define SW   44              // padded smem row stride (16B-aligned rows)
#define HR   42              // halo rows
#define NTHREADS 256
#define GX (IMGW / TW)       // 16
#define GY (IMGH / TH)       // 16
#define GZ 48                // 16*3
#define NBLOCKS (GX * GY * GZ)   // 12288
#define NSLOT 128

// Normalized 11-tap Gaussian, sigma=1.5
#define W0 0.00102838f
#define W1 0.00759876f
#define W2 0.03600077f
#define W3 0.10936069f
#define W4 0.21300554f
#define W5 0.26601173f

__device__ double   g_slots[NSLOT];   // zero-init at load; self-reset per run
__device__ unsigned g_count;          // zero-init at load; self-reset per run

__device__ __forceinline__ int reflect_idx(int i, int n) {
    if (i < 0) i = -i;
    if (i >= n) i = 2 * n - 2 - i;
    return i;
}

__device__ __forceinline__ constexpr float WT(int k) {
    return (k == 0 || k == 10) ? W0
         : (k == 1 || k == 9)  ? W1
         : (k == 2 || k == 8)  ? W2
         : (k == 3 || k == 7)  ? W3
         : (k == 4 || k == 6)  ? W4
         : W5;
}

__global__ __launch_bounds__(NTHREADS, 5)
void ssim_fused_kernel(const float* __restrict__ img1,
                       const float* __restrict__ img2,
                       float* __restrict__ out) {
    __shared__ float s1[HR * SW];          // 1848
    __shared__ float s2[HR * SW];          // 1848
    __shared__ float hb[5][HR * TW];       // 5 x 1344
    __shared__ float ws[NTHREADS / 32];
    __shared__ double dsum[4];
    __shared__ int s_isLast;

    const int tid = threadIdx.x;
    const int img = blockIdx.z;
    const int tx0 = blockIdx.x * TW;
    const int ty0 = blockIdx.y * TH;

    const float* a = img1 + (size_t)img * (IMGW * IMGH);
    const float* b = img2 + (size_t)img * (IMGW * IMGH);

    // ---- load halo tile (reflect padding), padded row stride SW ----
    for (int idx = tid; idx < HR * HW; idx += NTHREADS) {
        int r = idx / HW;
        int c = idx - r * HW;
        int gy = reflect_idx(ty0 + r - HALO, IMGH);
        int gx = reflect_idx(tx0 + c - HALO, IMGW);
        s1[r * SW + c] = a[gy * IMGW + gx];
        s2[r * SW + c] = b[gy * IMGW + gx];
    }
    __syncthreads();

    // ---- horizontal pass: HR rows x 8 col-groups of 4 = 336 tasks ----
    for (int task = tid; task < HR * (TW / 4); task += NTHREADS) {
        int r  = task >> 3;
        int c0 = (task & 7) << 2;
        const float* p1 = s1 + r * SW + c0;   // 16B aligned (44r+c0 ≡ 0 mod 4)
        const float* p2 = s2 + r * SW + c0;

        // vectorized window loads: 3x float4 + 1x float2 per image
        float va[14], vb[14];
        {
            float4 q0 = *(const float4*)(p1 + 0);
            float4 q1 = *(const float4*)(p1 + 4);
            float4 q2 = *(const float4*)(p1 + 8);
            float2 q3 = *(const float2*)(p1 + 12);
            va[0]=q0.x; va[1]=q0.y; va[2]=q0.z; va[3]=q0.w;
            va[4]=q1.x; va[5]=q1.y; va[6]=q1.z; va[7]=q1.w;
            va[8]=q2.x; va[9]=q2.y; va[10]=q2.z; va[11]=q2.w;
            va[12]=q3.x; va[13]=q3.y;
        }
        {
            float4 q0 = *(const float4*)(p2 + 0);
            float4 q1 = *(const float4*)(p2 + 4);
            float4 q2 = *(const float4*)(p2 + 8);
            float2 q3 = *(const float2*)(p2 + 12);
            vb[0]=q0.x; vb[1]=q0.y; vb[2]=q0.z; vb[3]=q0.w;
            vb[4]=q1.x; vb[5]=q1.y; vb[6]=q1.z; vb[7]=q1.w;
            vb[8]=q2.x; vb[9]=q2.y; vb[10]=q2.z; vb[11]=q2.w;
            vb[12]=q3.x; vb[13]=q3.y;
        }

        float aa[14], bb[14], ab[14];
#pragma unroll
        for (int i = 0; i < 14; i++) {
            aa[i] = va[i] * va[i];
            bb[i] = vb[i] * vb[i];
            ab[i] = va[i] * vb[i];
        }

        float v1[4]  = {0.f, 0.f, 0.f, 0.f};
        float v2[4]  = {0.f, 0.f, 0.f, 0.f};
        float v11[4] = {0.f, 0.f, 0.f, 0.f};
        float v22[4] = {0.f, 0.f, 0.f, 0.f};
        float v12[4] = {0.f, 0.f, 0.f, 0.f};
#pragma unroll
        for (int k = 0; k < 11; k++) {
            const float wk = WT(k);   // literal -> FFMA-imm (rt 1)
#pragma unroll
            for (int j = 0; j < 4; j++) {
                v1[j]  = fmaf(wk, va[j + k], v1[j]);
                v2[j]  = fmaf(wk, vb[j + k], v2[j]);
                v11[j] = fmaf(wk, aa[j + k], v11[j]);
                v22[j] = fmaf(wk, bb[j + k], v22[j]);
                v12[j] = fmaf(wk, ab[j + k], v12[j]);
            }
        }
        int o = r * TW + c0;                  // word addr 32r+4L: conflict-free STS.128
        *(float4*)&hb[0][o] = make_float4(v1[0],  v1[1],  v1[2],  v1[3]);
        *(float4*)&hb[1][o] = make_float4(v2[0],  v2[1],  v2[2],  v2[3]);
        *(float4*)&hb[2][o] = make_float4(v11[0], v11[1], v11[2], v11[3]);
        *(float4*)&hb[3][o] = make_float4(v22[0], v22[1], v22[2], v22[3]);
        *(float4*)&hb[4][o] = make_float4(v12[0], v12[1], v12[2], v12[3]);
    }
    __syncthreads();

    // ---- vertical pass + SSIM: 32 cols x 8 strips of 4 rows ----
    const int tx = tid & 31;
    const int r0 = (tid >> 5) << 2;   // 0,4,...,28

    float m[5][4];
#pragma unroll
    for (int c = 0; c < 5; c++) {
        const float* hc = hb[c];
        float acc0 = 0.f, acc1 = 0.f, acc2 = 0.f, acc3 = 0.f;
#pragma unroll
        for (int k = 0; k < 14; k++) {
            float hv = hc[(r0 + k) * TW + tx];   // stride-1 across lanes: conflict-free
            if (k <= 10)           acc0 = fmaf(WT(k),     hv, acc0);
            if (k >= 1 && k <= 11) acc1 = fmaf(WT(k - 1), hv, acc1);
            if (k >= 2 && k <= 12) acc2 = fmaf(WT(k - 2), hv, acc2);
            if (k >= 3)            acc3 = fmaf(WT(k - 3), hv, acc3);
        }
        m[c][0] = acc0; m[c][1] = acc1; m[c][2] = acc2; m[c][3] = acc3;
    }

    const float C1 = 1e-4f;
    const float C2 = 9e-4f;
    float lsum = 0.f;
#pragma unroll
    for (int j = 0; j < 4; j++) {
        float mu1 = m[0][j], mu2 = m[1][j];
        float e11 = m[2][j], e22 = m[3][j], e12 = m[4][j];
        float mu1sq = mu1 * mu1;
        float mu2sq = mu2 * mu2;
        float mu12  = mu1 * mu2;
        float sg1  = e11 - mu1sq;
        float sg2  = e22 - mu2sq;
        float sg12 = e12 - mu12;
        float num = fmaf(2.f, mu12, C1) * fmaf(2.f, sg12, C2);
        float den = (mu1sq + mu2sq + C1) * (sg1 + sg2 + C2);
        float v = __fdividef(num, den);
        v = fminf(fmaxf(v, 0.f), 1.f);
        lsum += v;
    }

    // ---- block reduction ----
#pragma unroll
    for (int off = 16; off > 0; off >>= 1)
        lsum += __shfl_xor_sync(0xffffffff, lsum, off);
    if ((tid & 31) == 0) ws[tid >> 5] = lsum;
    __syncthreads();

    if (tid == 0) {
        float s = 0.f;
#pragma unroll
        for (int i = 0; i < NTHREADS / 32; i++) s += ws[i];
        const int bid = blockIdx.x + GX * (blockIdx.y + GY * blockIdx.z);
        atomicAdd(&g_slots[bid & (NSLOT - 1)], (double)s);
        __threadfence();
        unsigned old = atomicAdd(&g_count, 1u);
        s_isLast = (old == NBLOCKS - 1);
    }
    __syncthreads();

    // ---- last block: finalize + reset for next graph replay ----
    if (s_isLast) {
        double v = 0.0;
        if (tid < NSLOT) v = ((volatile double*)g_slots)[tid];
#pragma unroll
        for (int off = 16; off > 0; off >>= 1)
            v += __shfl_xor_sync(0xffffffff, v, off);
        if (tid < NSLOT && (tid & 31) == 0) dsum[tid >> 5] = v;
        __syncthreads();
        if (tid == 0) {
            double total = dsum[0] + dsum[1] + dsum[2] + dsum[3];
            const double npix = 16.0 * 3.0 * 512.0 * 512.0;
            out[0] = (float)(1.0 - total / npix);
            g_count = 0;
        }
        if (tid < NSLOT) g_slots[tid] = 0.0;
    }
}

extern "C" void kernel_launch(void* const* d_in, const int* in_sizes, int n_in,
                              void* d_out, int out_size) {
    const float* img1 = (const float*)d_in[0];
    const float* img2 = (const float*)d_in[1];
    float* out = (float*)d_out;

    dim3 grid(GX, GY, GZ);
    ssim_fused_kernel<<<grid, NTHREADS>>>(img1, img2, out);
}

// round 5
// speedup vs baseline: 1.2552x; 1.0441x over previous
#include <cuda_runtime.h>

// ---------------------------------------------------------------------------
// SSIM loss, single fused kernel, packed-f32x2 (FFMA2) version:
//   - img1/img2 stored interleaved (a,b) in smem; the (mu1,mu2) and (E11,E22)
//     conv streams run on fma.rn.f32x2 / mul.rn.f32x2 (one instr, two lanes)
//   - E12 stream stays scalar FFMA-imm
//   - 32x32 tiles, 42x44(float2) halo, SoA blur buffers, 5 CTA/SM
//   - 128-slot double atomics + last-block-done finalize (self-resetting)
// ---------------------------------------------------------------------------

typedef unsigned long long u64;

#define IMGW 512
#define IMGH 512
#define TW   32
#define TH   32
#define HALO 5
#define HW   42              // halo width (elems)
#define SW2  44              // padded smem row stride in float2 units
#define HR   42              // halo rows
#define NTHREADS 256
#define GX 16
#define GY 16
#define GZ 48
#define NBLOCKS (GX * GY * GZ)   // 12288
#define NSLOT 128

// Normalized 11-tap Gaussian, sigma=1.5
#define W0 0.00102838f
#define W1 0.00759876f
#define W2 0.03600077f
#define W3 0.10936069f
#define W4 0.21300554f
#define W5 0.26601173f

__device__ double   g_slots[NSLOT];
__device__ unsigned g_count;

__device__ __forceinline__ int reflect_idx(int i, int n) {
    if (i < 0) i = -i;
    if (i >= n) i = 2 * n - 2 - i;
    return i;
}

__device__ __forceinline__ constexpr float WT(int k) {
    return (k == 0 || k == 10) ? W0
         : (k == 1 || k == 9)  ? W1
         : (k == 2 || k == 8)  ? W2
         : (k == 3 || k == 7)  ? W3
         : (k == 4 || k == 6)  ? W4
         : W5;
}
__device__ __forceinline__ constexpr int WI(int k) { return (k < 6) ? k : 10 - k; }

// ---- packed f32x2 helpers (sm_100+) ----
__device__ __forceinline__ u64 pack2(float x, float y) {
    u64 r;
    asm("mov.b64 %0, {%1, %2};" : "=l"(r) : "f"(x), "f"(y));
    return r;
}
__device__ __forceinline__ void unpack2(u64 v, float& x, float& y) {
    asm("mov.b64 {%0, %1}, %2;" : "=f"(x), "=f"(y) : "l"(v));
}
__device__ __forceinline__ void fma2(u64& d, u64 a, u64 b) {
    asm("fma.rn.f32x2 %0, %1, %2, %0;" : "+l"(d) : "l"(a), "l"(b));
}
__device__ __forceinline__ u64 mul2(u64 a, u64 b) {
    u64 d;
    asm("mul.rn.f32x2 %0, %1, %2;" : "=l"(d) : "l"(a), "l"(b));
    return d;
}

__global__ __launch_bounds__(NTHREADS, 5)
void ssim_fused_kernel(const float* __restrict__ img1,
                       const float* __restrict__ img2,
                       float* __restrict__ out) {
    __shared__ u64   s12[HR * SW2];       // interleaved (a,b): 14784 B
    __shared__ u64   hb12[HR * TW];       // (mu1,mu2) h-blur: 10752 B
    __shared__ u64   hbsq[HR * TW];       // (E11,E22) h-blur: 10752 B
    __shared__ float hbab[HR * TW];       // E12 h-blur:        5376 B
    __shared__ float ws[NTHREADS / 32];
    __shared__ double dsum[4];
    __shared__ int s_isLast;

    const int tid = threadIdx.x;
    const int img = blockIdx.z;
    const int tx0 = blockIdx.x * TW;
    const int ty0 = blockIdx.y * TH;

    const float* a = img1 + (size_t)img * (IMGW * IMGH);
    const float* b = img2 + (size_t)img * (IMGW * IMGH);

    // packed weight pairs (hoisted constants)
    const u64 wp[6] = { pack2(W0, W0), pack2(W1, W1), pack2(W2, W2),
                        pack2(W3, W3), pack2(W4, W4), pack2(W5, W5) };

    // ---- load halo tile (reflect padding), interleaved pairs ----
    for (int idx = tid; idx < HR * HW; idx += NTHREADS) {
        int r = idx / HW;
        int c = idx - r * HW;
        int gy = reflect_idx(ty0 + r - HALO, IMGH);
        int gx = reflect_idx(tx0 + c - HALO, IMGW);
        int g = gy * IMGW + gx;
        s12[r * SW2 + c] = pack2(a[g], b[g]);
    }
    __syncthreads();

    // ---- horizontal pass: HR rows x 8 col-groups of 4 = 336 tasks ----
    for (int task = tid; task < HR * (TW / 4); task += NTHREADS) {
        int r  = task >> 3;
        int c0 = (task & 7) << 2;
        const u64* p = s12 + r * SW2 + c0;   // 16B aligned (SW2 even, c0%4==0)

        u64 vab[14];
#pragma unroll
        for (int i = 0; i < 7; i++) {
            ulonglong2 q = *(const ulonglong2*)(p + 2 * i);
            vab[2 * i] = q.x; vab[2 * i + 1] = q.y;
        }
        u64 pp[14];
        float ab[14];
#pragma unroll
        for (int i = 0; i < 14; i++) {
            pp[i] = mul2(vab[i], vab[i]);          // (a^2, b^2)
            float x, y; unpack2(vab[i], x, y);
            ab[i] = x * y;                          // a*b
        }

        u64 a12[4] = {0, 0, 0, 0};
        u64 asq[4] = {0, 0, 0, 0};
        float aab[4] = {0.f, 0.f, 0.f, 0.f};
#pragma unroll
        for (int k = 0; k < 11; k++) {
            const u64  wk2 = wp[WI(k)];
            const float wk = WT(k);
#pragma unroll
            for (int j = 0; j < 4; j++) {
                fma2(a12[j], vab[j + k], wk2);
                fma2(asq[j], pp[j + k],  wk2);
                aab[j] = fmaf(wk, ab[j + k], aab[j]);   // FFMA-imm
            }
        }
        int o = r * TW + c0;
        *(ulonglong2*)&hb12[o]     = make_ulonglong2(a12[0], a12[1]);
        *(ulonglong2*)&hb12[o + 2] = make_ulonglong2(a12[2], a12[3]);
        *(ulonglong2*)&hbsq[o]     = make_ulonglong2(asq[0], asq[1]);
        *(ulonglong2*)&hbsq[o + 2] = make_ulonglong2(asq[2], asq[3]);
        *(float4*)&hbab[o] = make_float4(aab[0], aab[1], aab[2], aab[3]);
    }
    __syncthreads();

    // ---- vertical pass + SSIM: 32 cols x 8 strips of 4 rows ----
    const int tx = tid & 31;
    const int r0 = (tid >> 5) << 2;   // 0,4,...,28

    u64 m12[4] = {0, 0, 0, 0};
    u64 msq[4] = {0, 0, 0, 0};
    float mab[4] = {0.f, 0.f, 0.f, 0.f};
#pragma unroll
    for (int k = 0; k < 14; k++) {
        int idx = (r0 + k) * TW + tx;
        u64 h12 = hb12[idx];
        u64 hsq = hbsq[idx];
        float hab = hbab[idx];
        if (k <= 10) {
            fma2(m12[0], h12, wp[WI(k)]);
            fma2(msq[0], hsq, wp[WI(k)]);
            mab[0] = fmaf(WT(k), hab, mab[0]);
        }
        if (k >= 1 && k <= 11) {
            fma2(m12[1], h12, wp[WI(k - 1)]);
            fma2(msq[1], hsq, wp[WI(k - 1)]);
            mab[1] = fmaf(WT(k - 1), hab, mab[1]);
        }
        if (k >= 2 && k <= 12) {
            fma2(m12[2], h12, wp[WI(k - 2)]);
            fma2(msq[2], hsq, wp[WI(k - 2)]);
            mab[2] = fmaf(WT(k - 2), hab, mab[2]);
        }
        if (k >= 3) {
            fma2(m12[3], h12, wp[WI(k - 3)]);
            fma2(msq[3], hsq, wp[WI(k - 3)]);
            mab[3] = fmaf(WT(k - 3), hab, mab[3]);
        }
    }

    const float C1 = 1e-4f;
    const float C2 = 9e-4f;
    float lsum = 0.f;
#pragma unroll
    for (int j = 0; j < 4; j++) {
        float mu1, mu2, e11, e22;
        unpack2(m12[j], mu1, mu2);
        unpack2(msq[j], e11, e22);
        float e12 = mab[j];
        float mu1sq = mu1 * mu1;
        float mu2sq = mu2 * mu2;
        float mu12  = mu1 * mu2;
        float sg1  = e11 - mu1sq;
        float sg2  = e22 - mu2sq;
        float sg12 = e12 - mu12;
        float num = fmaf(2.f, mu12, C1) * fmaf(2.f, sg12, C2);
        float den = (mu1sq + mu2sq + C1) * (sg1 + sg2 + C2);
        float v = __fdividef(num, den);
        v = fminf(fmaxf(v, 0.f), 1.f);
        lsum += v;
    }

    // ---- block reduction ----
#pragma unroll
    for (int off = 16; off > 0; off >>= 1)
        lsum += __shfl_xor_sync(0xffffffff, lsum, off);
    if ((tid & 31) == 0) ws[tid >> 5] = lsum;
    __syncthreads();

    if (tid == 0) {
        float s = 0.f;
#pragma unroll
        for (int i = 0; i < NTHREADS / 32; i++) s += ws[i];
        const int bid = blockIdx.x + GX * (blockIdx.y + GY * blockIdx.z);
        atomicAdd(&g_slots[bid & (NSLOT - 1)], (double)s);
        __threadfence();
        unsigned old = atomicAdd(&g_count, 1u);
        s_isLast = (old == NBLOCKS - 1);
    }
    __syncthreads();

    // ---- last block: finalize + reset for next graph replay ----
    if (s_isLast) {
        double v = 0.0;
        if (tid < NSLOT) v = ((volatile double*)g_slots)[tid];
#pragma unroll
        for (int off = 16; off > 0; off >>= 1)
            v += __shfl_xor_sync(0xffffffff, v, off);
        if (tid < NSLOT && (tid & 31) == 0) dsum[tid >> 5] = v;
        __syncthreads();
        if (tid == 0) {
            double total = dsum[0] + dsum[1] + dsum[2] + dsum[3];
            const double npix = 16.0 * 3.0 * 512.0 * 512.0;
            out[0] = (float)(1.0 - total / npix);
            g_count = 0;
        }
        if (tid < NSLOT) g_slots[tid] = 0.0;
    }
}

extern "C" void kernel_launch(void* const* d_in, const int* in_sizes, int n_in,
                              void* d_out, int out_size) {
    const float* img1 = (const float*)d_in[0];
    const float* img2 = (const float*)d_in[1];
    float* out = (float*)d_out;

    dim3 grid(GX, GY, GZ);
    ssim_fused_kernel<<<grid, NTHREADS>>>(img1, img2, out);
}

// round 6
// speedup vs baseline: 1.2877x; 1.0259x over previous
#include <cuda_runtime.h>

// ---------------------------------------------------------------------------
// SSIM loss, single fused kernel, f32x2 + 8-row vertical strips:
//   - interleaved (a,b) halo; (mu1,mu2),(E11,E22) streams on fma.rn.f32x2
//   - E12 stream packed over output pairs in horizontal pass
//   - vertical pass: 128 threads, strips of 8 rows (2.25 LDS reads/output),
//     3 sequential channel passes to bound register pressure
//   - 128-slot double atomics + last-block-done finalize (self-resetting)
// ---------------------------------------------------------------------------

typedef unsigned long long u64;

#define IMGW 512
#define IMGH 512
#define TW   32
#define TH   32
#define HALO 5
#define HW   42
#define SW2  44              // padded smem row stride (float2 units)
#define HR   42
#define NTHREADS 256
#define GX 16
#define GY 16
#define GZ 48
#define NBLOCKS (GX * GY * GZ)
#define NSLOT 128

#define W0 0.00102838f
#define W1 0.00759876f
#define W2 0.03600077f
#define W3 0.10936069f
#define W4 0.21300554f
#define W5 0.26601173f

__device__ double   g_slots[NSLOT];
__device__ unsigned g_count;

__device__ __forceinline__ int reflect_idx(int i, int n) {
    if (i < 0) i = -i;
    if (i >= n) i = 2 * n - 2 - i;
    return i;
}

__device__ __forceinline__ constexpr float WT(int k) {
    return (k == 0 || k == 10) ? W0
         : (k == 1 || k == 9)  ? W1
         : (k == 2 || k == 8)  ? W2
         : (k == 3 || k == 7)  ? W3
         : (k == 4 || k == 6)  ? W4
         : W5;
}
__device__ __forceinline__ constexpr int WI(int k) { return (k < 6) ? k : 10 - k; }

// ---- packed f32x2 helpers ----
__device__ __forceinline__ u64 pack2(float x, float y) {
    u64 r;
    asm("mov.b64 %0, {%1, %2};" : "=l"(r) : "f"(x), "f"(y));
    return r;
}
__device__ __forceinline__ void unpack2(u64 v, float& x, float& y) {
    asm("mov.b64 {%0, %1}, %2;" : "=f"(x), "=f"(y) : "l"(v));
}
__device__ __forceinline__ void fma2(u64& d, u64 a, u64 b) {
    asm("fma.rn.f32x2 %0, %1, %2, %0;" : "+l"(d) : "l"(a), "l"(b));
}
__device__ __forceinline__ u64 mul2(u64 a, u64 b) {
    u64 d;
    asm("mul.rn.f32x2 %0, %1, %2;" : "=l"(d) : "l"(a), "l"(b));
    return d;
}

__global__ __launch_bounds__(NTHREADS, 5)
void ssim_fused_kernel(const float* __restrict__ img1,
                       const float* __restrict__ img2,
                       float* __restrict__ out) {
    __shared__ u64   s12[HR * SW2];       // interleaved (a,b)
    __shared__ u64   hb12[HR * TW];       // (mu1,mu2) h-blur
    __shared__ u64   hbsq[HR * TW];       // (E11,E22) h-blur
    __shared__ float hbab[HR * TW];       // E12 h-blur
    __shared__ float ws[NTHREADS / 32];
    __shared__ double dsum[4];
    __shared__ int s_isLast;

    const int tid = threadIdx.x;
    const int img = blockIdx.z;
    const int tx0 = blockIdx.x * TW;
    const int ty0 = blockIdx.y * TH;

    const float* a = img1 + (size_t)img * (IMGW * IMGH);
    const float* b = img2 + (size_t)img * (IMGW * IMGH);

    const u64 wp[6] = { pack2(W0, W0), pack2(W1, W1), pack2(W2, W2),
                        pack2(W3, W3), pack2(W4, W4), pack2(W5, W5) };

    // ---- load halo tile (reflect padding), interleaved pairs ----
    for (int idx = tid; idx < HR * HW; idx += NTHREADS) {
        int r = idx / HW;
        int c = idx - r * HW;
        int gy = reflect_idx(ty0 + r - HALO, IMGH);
        int gx = reflect_idx(tx0 + c - HALO, IMGW);
        int g = gy * IMGW + gx;
        s12[r * SW2 + c] = pack2(a[g], b[g]);
    }
    __syncthreads();

    // ---- horizontal pass: 42 rows x 8 col-groups of 4 = 336 tasks ----
    for (int task = tid; task < HR * (TW / 4); task += NTHREADS) {
        int r  = task >> 3;
        int c0 = (task & 7) << 2;
        const u64* p = s12 + r * SW2 + c0;

        u64 vab[14];
#pragma unroll
        for (int i = 0; i < 7; i++) {
            ulonglong2 q = *(const ulonglong2*)(p + 2 * i);
            vab[2 * i] = q.x; vab[2 * i + 1] = q.y;
        }
        u64 pp[14];
        float ab[14];
#pragma unroll
        for (int i = 0; i < 14; i++) {
            pp[i] = mul2(vab[i], vab[i]);          // (a^2, b^2)
            float x, y; unpack2(vab[i], x, y);
            ab[i] = x * y;
        }
        u64 abp[13];
#pragma unroll
        for (int i = 0; i < 13; i++) abp[i] = pack2(ab[i], ab[i + 1]);

        u64 a12[4] = {0, 0, 0, 0};
        u64 asq[4] = {0, 0, 0, 0};
        u64 aab01 = 0, aab23 = 0;
#pragma unroll
        for (int k = 0; k < 11; k++) {
            const u64 wk2 = wp[WI(k)];
#pragma unroll
            for (int j = 0; j < 4; j++) {
                fma2(a12[j], vab[j + k], wk2);
                fma2(asq[j], pp[j + k],  wk2);
            }
            fma2(aab01, abp[k],     wk2);   // (E12 out0, out1)
            fma2(aab23, abp[k + 2], wk2);   // (E12 out2, out3)
        }
        int o = r * TW + c0;
        *(ulonglong2*)&hb12[o]     = make_ulonglong2(a12[0], a12[1]);
        *(ulonglong2*)&hb12[o + 2] = make_ulonglong2(a12[2], a12[3]);
        *(ulonglong2*)&hbsq[o]     = make_ulonglong2(asq[0], asq[1]);
        *(ulonglong2*)&hbsq[o + 2] = make_ulonglong2(asq[2], asq[3]);
        *(ulonglong2*)&hbab[o]     = make_ulonglong2(aab01, aab23);
    }
    __syncthreads();

    // ---- vertical pass + SSIM: 128 threads, 32 cols x 4 strips of 8 rows ----
    float lsum = 0.f;
    const int tx  = tid & 31;
    const int sid = tid >> 5;            // warp id 0..7

    if (sid < 4) {
        const int r0 = sid << 3;         // 0,8,16,24; reads rows r0..r0+17
        float pA[8], pB[8], pC[8];       // mu12, mu1^2+mu2^2, e11+e22

        // pass 1: (mu1, mu2)
        {
            u64 m[8] = {0, 0, 0, 0, 0, 0, 0, 0};
            const u64* p = hb12 + r0 * TW + tx;
#pragma unroll
            for (int k = 0; k < 18; k++) {
                u64 h = p[k * TW];
#pragma unroll
                for (int j = 0; j < 8; j++)
                    if (k - j >= 0 && k - j <= 10) fma2(m[j], h, wp[WI(k - j)]);
            }
#pragma unroll
            for (int j = 0; j < 8; j++) {
                float mu1, mu2; unpack2(m[j], mu1, mu2);
                pA[j] = mu1 * mu2;
                pB[j] = fmaf(mu1, mu1, mu2 * mu2);
            }
        }
        // pass 2: (E11, E22)
        {
            u64 m[8] = {0, 0, 0, 0, 0, 0, 0, 0};
            const u64* p = hbsq + r0 * TW + tx;
#pragma unroll
            for (int k = 0; k < 18; k++) {
                u64 h = p[k * TW];
#pragma unroll
                for (int j = 0; j < 8; j++)
                    if (k - j >= 0 && k - j <= 10) fma2(m[j], h, wp[WI(k - j)]);
            }
#pragma unroll
            for (int j = 0; j < 8; j++) {
                float e11, e22; unpack2(m[j], e11, e22);
                pC[j] = e11 + e22;
            }
        }
        // pass 3: E12 + SSIM
        {
            float m[8] = {0.f, 0.f, 0.f, 0.f, 0.f, 0.f, 0.f, 0.f};
            const float* p = hbab + r0 * TW + tx;
#pragma unroll
            for (int k = 0; k < 18; k++) {
                float h = p[k * TW];
#pragma unroll
                for (int j = 0; j < 8; j++)
                    if (k - j >= 0 && k - j <= 10) m[j] = fmaf(WT(k - j), h, m[j]);
            }
            const float C1 = 1e-4f;
            const float C2 = 9e-4f;
#pragma unroll
            for (int j = 0; j < 8; j++) {
                float mu12 = pA[j];
                float sg12 = m[j] - mu12;
                float num = fmaf(2.f, mu12, C1) * fmaf(2.f, sg12, C2);
                float den = (pB[j] + C1) * (pC[j] - pB[j] + C2);
                float v = __fdividef(num, den);
                v = fminf(fmaxf(v, 0.f), 1.f);
                lsum += v;
            }
        }
    }

    // ---- block reduction ----
#pragma unroll
    for (int off = 16; off > 0; off >>= 1)
        lsum += __shfl_xor_sync(0xffffffff, lsum, off);
    if ((tid & 31) == 0) ws[tid >> 5] = lsum;
    __syncthreads();

    if (tid == 0) {
        float s = 0.f;
#pragma unroll
        for (int i = 0; i < NTHREADS / 32; i++) s += ws[i];
        const int bid = blockIdx.x + GX * (blockIdx.y + GY * blockIdx.z);
        atomicAdd(&g_slots[bid & (NSLOT - 1)], (double)s);
        __threadfence();
        unsigned old = atomicAdd(&g_count, 1u);
        s_isLast = (old == NBLOCKS - 1);
    }
    __syncthreads();

    // ---- last block: finalize + reset for next graph replay ----
    if (s_isLast) {
        double v = 0.0;
        if (tid < NSLOT) v = ((volatile double*)g_slots)[tid];
#pragma unroll
        for (int off = 16; off > 0; off >>= 1)
            v += __shfl_xor_sync(0xffffffff, v, off);
        if (tid < NSLOT && (tid & 31) == 0) dsum[tid >> 5] = v;
        __syncthreads();
        if (tid == 0) {
            double total = dsum[0] + dsum[1] + dsum[2] + dsum[3];
            const double npix = 16.0 * 3.0 * 512.0 * 512.0;
            out[0] = (float)(1.0 - total / npix);
            g_count = 0;
        }
        if (tid < NSLOT) g_slots[tid] = 0.0;
    }
}

extern "C" void kernel_launch(void* const* d_in, const int* in_sizes, int n_in,
                              void* d_out, int out_size) {
    const float* img1 = (const float*)d_in[0];
    const float* img2 = (const float*)d_in[1];
    float* out = (float*)d_out;

    dim3 grid(GX, GY, GZ);
    ssim_fused_kernel<<<grid, NTHREADS>>>(img1, img2, out);
}

// round 8
// speedup vs baseline: 1.6747x; 1.3005x over previous
#include <cuda_runtime.h>

// ---------------------------------------------------------------------------
// SSIM loss, single fused kernel, R7:
//   - halo load: fast path (interior blocks, no div/reflect, coalesced) +
//     slow path (border blocks)
//   - channels: (mu1,mu2) packed f32x2  and  (a^2+b^2, a*b) packed f32x2
//     (blur is linear -> e11+e22 blurred jointly; epilogue never needs them
//      separately)
//   - vertical pass: 2 packed passes over 8-row strips (128 threads)
//   - 128-slot double atomics + last-block-done finalize (self-resetting)
// ---------------------------------------------------------------------------

typedef unsigned long long u64;

#define IMGW 512
#define IMGH 512
#define TW   32
#define TH   32
#define HALO 5
#define HW   42
#define SW2  44              // padded smem row stride (float2 units)
#define HR   42
#define NTHREADS 256
#define GX 16
#define GY 16
#define GZ 48
#define NBLOCKS (GX * GY * GZ)
#define NSLOT 128

#define W0 0.00102838f
#define W1 0.00759876f
#define W2 0.03600077f
#define W3 0.10936069f
#define W4 0.21300554f
#define W5 0.26601173f

__device__ double   g_slots[NSLOT];
__device__ unsigned g_count;

__device__ __forceinline__ int reflect_idx(int i, int n) {
    if (i < 0) i = -i;
    if (i >= n) i = 2 * n - 2 - i;
    return i;
}

__device__ __forceinline__ constexpr float WT(int k) {
    return (k == 0 || k == 10) ? W0
         : (k == 1 || k == 9)  ? W1
         : (k == 2 || k == 8)  ? W2
         : (k == 3 || k == 7)  ? W3
         : (k == 4 || k == 6)  ? W4
         : W5;
}
__device__ __forceinline__ constexpr int WI(int k) { return (k < 6) ? k : 10 - k; }

// ---- packed f32x2 helpers ----
__device__ __forceinline__ u64 pack2(float x, float y) {
    u64 r;
    asm("mov.b64 %0, {%1, %2};" : "=l"(r) : "f"(x), "f"(y));
    return r;
}
__device__ __forceinline__ void unpack2(u64 v, float& x, float& y) {
    asm("mov.b64 {%0, %1}, %2;" : "=f"(x), "=f"(y) : "l"(v));
}
__device__ __forceinline__ void fma2(u64& d, u64 a, u64 b) {
    asm("fma.rn.f32x2 %0, %1, %2, %0;" : "+l"(d) : "l"(a), "l"(b));
}

__global__ __launch_bounds__(NTHREADS, 5)
void ssim_fused_kernel(const float* __restrict__ img1,
                       const float* __restrict__ img2,
                       float* __restrict__ out) {
    __shared__ u64 s12[HR * SW2];        // interleaved (a,b): 14784 B
    __shared__ u64 hb12[HR * TW];        // (mu1,mu2) h-blur: 10752 B
    __shared__ u64 hbsa[HR * TW];        // (a^2+b^2, a*b) h-blur: 10752 B
    __shared__ float ws[NTHREADS / 32];
    __shared__ double dsum[4];
    __shared__ int s_isLast;

    const int tid = threadIdx.x;
    const int img = blockIdx.z;
    const int tx0 = blockIdx.x * TW;
    const int ty0 = blockIdx.y * TH;

    const float* a = img1 + (size_t)img * (IMGW * IMGH);
    const float* b = img2 + (size_t)img * (IMGW * IMGH);

    const u64 wp[6] = { pack2(W0, W0), pack2(W1, W1), pack2(W2, W2),
                        pack2(W3, W3), pack2(W4, W4), pack2(W5, W5) };

    // ---- load halo tile ----
    const bool interior = (blockIdx.x > 0) & (blockIdx.x < GX - 1) &
                          (blockIdx.y > 0) & (blockIdx.y < GY - 1);
    if (interior) {
        // fast path: no reflect, incremental addressing, coalesced rows
        const float* pa = a + (ty0 - HALO) * IMGW + (tx0 - HALO);
        const float* pb = b + (ty0 - HALO) * IMGW + (tx0 - HALO);
        const int ct = tid & 31;         // column within row
        const int rt = tid >> 5;         // row 0..7
#pragma unroll
        for (int rr = 0; rr < 6; rr++) {
            int r = rt + rr * 8;
            if (r < HR) {
                int g = r * IMGW + ct;
                int s = r * SW2 + ct;
#pragma unroll
                for (int cc = 0; cc < 2; cc++) {
                    int c = ct + cc * 32;
                    if (c < HW)
                        s12[s + cc * 32] = pack2(pa[g + cc * 32], pb[g + cc * 32]);
                }
            }
        }
    } else {
        // border path: reflect padding
        for (int idx = tid; idx < HR * HW; idx += NTHREADS) {
            int r = idx / HW;
            int c = idx - r * HW;
            int gy = reflect_idx(ty0 + r - HALO, IMGH);
            int gx = reflect_idx(tx0 + c - HALO, IMGW);
            int g = gy * IMGW + gx;
            s12[r * SW2 + c] = pack2(a[g], b[g]);
        }
    }
    __syncthreads();

    // ---- horizontal pass: 42 rows x 8 col-groups of 4 = 336 tasks ----
    for (int task = tid; task < HR * (TW / 4); task += NTHREADS) {
        int r  = task >> 3;
        int c0 = (task & 7) << 2;
        const u64* p = s12 + r * SW2 + c0;

        u64 vab[14];
#pragma unroll
        for (int i = 0; i < 7; i++) {
            ulonglong2 q = *(const ulonglong2*)(p + 2 * i);
            vab[2 * i] = q.x; vab[2 * i + 1] = q.y;
        }
        u64 sa[14];                      // (a^2+b^2, a*b) per halo elem
#pragma unroll
        for (int i = 0; i < 14; i++) {
            float x, y; unpack2(vab[i], x, y);
            float ab = x * y;
            float ss = fmaf(x, x, y * y);
            sa[i] = pack2(ss, ab);
        }

        u64 a12[4] = {0, 0, 0, 0};
        u64 asa[4] = {0, 0, 0, 0};
#pragma unroll
        for (int k = 0; k < 11; k++) {
            const u64 wk2 = wp[WI(k)];
#pragma unroll
            for (int j = 0; j < 4; j++) {
                fma2(a12[j], vab[j + k], wk2);
                fma2(asa[j], sa[j + k],  wk2);
            }
        }
        int o = r * TW + c0;
        *(ulonglong2*)&hb12[o]     = make_ulonglong2(a12[0], a12[1]);
        *(ulonglong2*)&hb12[o + 2] = make_ulonglong2(a12[2], a12[3]);
        *(ulonglong2*)&hbsa[o]     = make_ulonglong2(asa[0], asa[1]);
        *(ulonglong2*)&hbsa[o + 2] = make_ulonglong2(asa[2], asa[3]);
    }
    __syncthreads();

    // ---- vertical pass + SSIM: 128 threads, 32 cols x 4 strips of 8 rows ----
    float lsum = 0.f;
    const int tx  = tid & 31;
    const int sid = tid >> 5;

    if (sid < 4) {
        const int r0 = sid << 3;         // 0,8,16,24; reads rows r0..r0+17
        float pA[8], pB[8];              // mu1*mu2, mu1^2+mu2^2

        // pass 1: (mu1, mu2)
        {
            u64 m[8] = {0, 0, 0, 0, 0, 0, 0, 0};
            const u64* p = hb12 + r0 * TW + tx;
#pragma unroll
            for (int k = 0; k < 18; k++) {
                u64 h = p[k * TW];
#pragma unroll
                for (int j = 0; j < 8; j++)
                    if (k - j >= 0 && k - j <= 10) fma2(m[j], h, wp[WI(k - j)]);
            }
#pragma unroll
            for (int j = 0; j < 8; j++) {
                float mu1, mu2; unpack2(m[j], mu1, mu2);
                pA[j] = mu1 * mu2;
                pB[j] = fmaf(mu1, mu1, mu2 * mu2);
            }
        }
        // pass 2: (a^2+b^2, a*b)  + SSIM epilogue
        {
            u64 m[8] = {0, 0, 0, 0, 0, 0, 0, 0};
            const u64* p = hbsa + r0 * TW + tx;
#pragma unroll
            for (int k = 0; k < 18; k++) {
                u64 h = p[k * TW];
#pragma unroll
                for (int j = 0; j < 8; j++)
                    if (k - j >= 0 && k - j <= 10) fma2(m[j], h, wp[WI(k - j)]);
            }
            const float C1 = 1e-4f;
            const float C2 = 9e-4f;
#pragma unroll
            for (int j = 0; j < 8; j++) {
                float ssb, e12; unpack2(m[j], ssb, e12);
                float mu12 = pA[j];
                float sg12 = e12 - mu12;
                float num = fmaf(2.f, mu12, C1) * fmaf(2.f, sg12, C2);
                float den = (pB[j] + C1) * (ssb - pB[j] + C2);
                float v = __fdividef(num, den);
                v = fminf(fmaxf(v, 0.f), 1.f);
                lsum += v;
            }
        }
    }

    // ---- block reduction ----
#pragma unroll
    for (int off = 16; off > 0; off >>= 1)
        lsum += __shfl_xor_sync(0xffffffff, lsum, off);
    if ((tid & 31) == 0) ws[tid >> 5] = lsum;
    __syncthreads();

    if (tid == 0) {
        float s = 0.f;
#pragma unroll
        for (int i = 0; i < NTHREADS / 32; i++) s += ws[i];
        const int bid = blockIdx.x + GX * (blockIdx.y + GY * blockIdx.z);
        atomicAdd(&g_slots[bid & (NSLOT - 1)], (double)s);
        __threadfence();
        unsigned old = atomicAdd(&g_count, 1u);
        s_isLast = (old == NBLOCKS - 1);
    }
    __syncthreads();

    // ---- last block: finalize + reset for next graph replay ----
    if (s_isLast) {
        double v = 0.0;
        if (tid < NSLOT) v = ((volatile double*)g_slots)[tid];
#pragma unroll
        for (int off = 16; off > 0; off >>= 1)
            v += __shfl_xor_sync(0xffffffff, v, off);
        if (tid < NSLOT && (tid & 31) == 0) dsum[tid >> 5] = v;
        __syncthreads();
        if (tid == 0) {
            double total = dsum[0] + dsum[1] + dsum[2] + dsum[3];
            const double npix = 16.0 * 3.0 * 512.0 * 512.0;
            out[0] = (float)(1.0 - total / npix);
            g_count = 0;
        }
        if (tid < NSLOT) g_slots[tid] = 0.0;
    }
}

extern "C" void kernel_launch(void* const* d_in, const int* in_sizes, int n_in,
                              void* d_out, int out_size) {
    const float* img1 = (const float*)d_in[0];
    const float* img2 = (const float*)d_in[1];
    float* out = (float*)d_out;

    dim3 grid(GX, GY, GZ);
    ssim_fused_kernel<<<grid, NTHREADS>>>(img1, img2, out);
}